// round 1
// baseline (speedup 1.0000x reference)
#include <cuda_runtime.h>
#include <math.h>

#define AHW   43264          // 208*208
#define NBOX  216320         // 5*208*208
#define WGRID 208
#define NCLS  80
#define HB    (1<<18)        // histogram buckets over p4 float bits >> 13
#define CAP   4096
#define KTOP  1024

__device__ __align__(16) unsigned g_hist[HB];
__device__ float               g_p4[NBOX];
__device__ float4              g_box[NBOX];
__device__ int                 g_cls[NBOX];
__device__ unsigned            g_T;
__device__ int                 g_count;
__device__ unsigned            g_cand[CAP];
__device__ unsigned long long  g_keys[CAP];
__device__ float4              g_tb[KTOP];
__device__ float               g_tconf[KTOP];
__device__ int                 g_tcls[KTOP];
__device__ unsigned            g_keep0[32];
__device__ unsigned            g_rowAny[32];
__device__ unsigned            g_sup[KTOP * 32];

// ---------------------------------------------------------------- zero state
__global__ void zero_kernel() {
    int i = blockIdx.x * blockDim.x + threadIdx.x;
    int stride = gridDim.x * blockDim.x;
    for (int q = i; q < HB; q += stride) g_hist[q] = 0u;
    if (i == 0) g_count = 0;
    if (i < 32) g_rowAny[i] = 0u;
}

// ---------------------------------------------------------------- decode
// grid (169, 5) x 256 threads : s = spatial idx, blockIdx.y = anchor
__global__ void decode_kernel(const float* __restrict__ x,
                              const float* __restrict__ anchors) {
    int s = blockIdx.x * 256 + threadIdx.x;      // 0..43263
    int a = blockIdx.y;                          // 0..4
    const float* px = x + (size_t)(a * (5 + NCLS)) * AHW + s;

    float p0 = __ldg(px);
    float p1 = __ldg(px + AHW);
    float p2 = __ldg(px + 2 * (size_t)AHW);
    float p3 = __ldg(px + 3 * (size_t)AHW);
    float p4 = __ldg(px + 4 * (size_t)AHW);

    // argmax over class logits, lowest index wins ties (strict >)
    const float* pc = px + 5 * (size_t)AHW;
    float best = __ldg(pc);
    int bi = 0;
#pragma unroll 8
    for (int k = 1; k < NCLS; k++) {
        float v = __ldg(pc + (size_t)k * AHW);
        if (v > best) { best = v; bi = k; }
    }

    int h = s / WGRID;
    int w = s - h * WGRID;
    float aw = __ldg(&anchors[a * 2]);
    float ah = __ldg(&anchors[a * 2 + 1]);

    float bx = (1.f / (1.f + expf(-p0)) + (float)w) * 32.f;
    float by = (1.f / (1.f + expf(-p1)) + (float)h) * 32.f;
    float bw = expf(p2) * aw * 32.f;
    float bh = expf(p3) * ah * 32.f;

    int n = a * AHW + s;
    g_box[n] = make_float4(bx, by, bw, bh);
    g_cls[n] = bi;
    g_p4[n]  = p4;

    if (p4 > 0.f) {   // conf > 0.5  <=>  logit > 0
        unsigned b = __float_as_uint(p4) >> 13;
        if (b >= HB) b = HB - 1;
        atomicAdd(&g_hist[b], 1u);
    }
}

// ---------------------------------------------------------------- threshold select
__global__ void scan_kernel() {
    __shared__ unsigned partial[1024];
    __shared__ unsigned s_chunk[256];
    __shared__ int s_sel[2];
    int t = threadIdx.x;
    unsigned sum = 0;
    const uint4* h4 = (const uint4*)g_hist;
#pragma unroll 4
    for (int i = 0; i < 64; i++) {
        uint4 v = h4[(size_t)t * 64 + i];
        sum += v.x + v.y + v.z + v.w;
    }
    partial[t] = sum;
    __syncthreads();
    if (t == 0) {
        unsigned acc = 0, before = 0; int c = -1;
        for (int q = 1023; q >= 0; q--) {
            before = acc; acc += partial[q];
            if (acc >= KTOP) { c = q; break; }
        }
        s_sel[0] = c; s_sel[1] = (int)before;
    }
    __syncthreads();
    int c = s_sel[0];
    if (c < 0) { if (t == 0) g_T = 0u; return; }
    if (t < 256) s_chunk[t] = g_hist[c * 256 + t];
    __syncthreads();
    if (t == 0) {
        unsigned acc = (unsigned)s_sel[1];
        int T = c * 256;
        for (int b = 255; b >= 0; b--) {
            acc += s_chunk[b];
            if (acc >= KTOP) { T = c * 256 + b; break; }
        }
        T -= 2;                 // safety margin (2 buckets = 2^14 ulps of p4)
        if (T < 0) T = 0;
        g_T = (unsigned)T;
    }
}

// ---------------------------------------------------------------- compact candidates
__global__ void compact_kernel() {
    int n = blockIdx.x * blockDim.x + threadIdx.x;
    if (n >= NBOX) return;
    float p = g_p4[n];
    if (p > 0.f) {
        unsigned b = __float_as_uint(p) >> 13;
        if (b >= HB) b = HB - 1;
        if (b >= g_T) {
            int pos = atomicAdd(&g_count, 1);
            if (pos < CAP) g_cand[pos] = (unsigned)n;
        }
    }
}

// ---------------------------------------------------------------- precise sigmoid keys
// fp64 sigmoid -> correctly-rounded fp32 conf. Only <=4096 elems, spread on 32 SMs.
__global__ void refine_kernel() {
    int s = blockIdx.x * blockDim.x + threadIdx.x;   // 0..4095
    int m = g_count; if (m > CAP) m = CAP;
    unsigned long long key = 0ull;
    if (s < m) {
        unsigned idx = g_cand[s];
        float p = g_p4[idx];
        double e = exp(-(double)p);
        float conf = (float)(1.0 / (1.0 + e));
        key = ((unsigned long long)__float_as_uint(conf) << 32)
              | (unsigned)(~idx);                    // tie-break: lower index = larger key
    }
    g_keys[s] = key;
}

// ---------------------------------------------------------------- bitonic sort 4096 (desc) + emit top arrays
__global__ void sort_kernel() {
    __shared__ unsigned long long sk[CAP];
    int tid = threadIdx.x;
#pragma unroll
    for (int m = 0; m < 4; m++) sk[tid + m * 1024] = g_keys[tid + m * 1024];
    __syncthreads();

    for (int k = 2; k <= CAP; k <<= 1) {
        for (int j = k >> 1; j > 0; j >>= 1) {
#pragma unroll
            for (int m = 0; m < 4; m++) {
                int t = tid + m * 1024;
                int ixj = t ^ j;
                if (ixj > t) {
                    unsigned long long a = sk[t], b = sk[ixj];
                    bool descSeg = ((t & k) == 0);
                    if (descSeg ? (a < b) : (a > b)) { sk[t] = b; sk[ixj] = a; }
                }
            }
            __syncthreads();
        }
    }

    // first 1024 threads write the top-K payloads
    unsigned long long key = sk[tid];
    bool valid = (key != 0ull);
    float4 b4 = make_float4(0.f, 0.f, 0.f, 0.f);
    int cl = 0; float conf = 0.f;
    if (valid) {
        unsigned idx = ~(unsigned)(key & 0xFFFFFFFFull);
        b4   = g_box[idx];
        cl   = g_cls[idx];
        conf = __uint_as_float((unsigned)(key >> 32));
    }
    g_tb[tid]    = b4;
    g_tcls[tid]  = cl;
    g_tconf[tid] = conf;
    unsigned wmask = __ballot_sync(0xffffffffu, valid);
    if ((tid & 31) == 0) g_keep0[tid >> 5] = wmask;
}

// ---------------------------------------------------------------- suppression matrix
// block i computes row i: suppress bits for all j (ballot -> 32 words)
__global__ void matrix_kernel() {
    int i = blockIdx.x;
    int j = threadIdx.x;
    __shared__ float4 bi;
    __shared__ int cli;
    __shared__ unsigned s_any;
    if (j == 0) { bi = g_tb[i]; cli = g_tcls[i]; s_any = 0u; }
    __syncthreads();

    float4 bj = g_tb[j];
    int clj = g_tcls[j];
    bool sup = false;
    if (j > i && clj == cli) {
        // faithful to reference: (c - s)/2 parenthesization
        float x1min = (bi.x - bi.z) * 0.5f, y1min = (bi.y - bi.w) * 0.5f;
        float x1max = (bi.x + bi.z) * 0.5f, y1max = (bi.y + bi.w) * 0.5f;
        float x2min = (bj.x - bj.z) * 0.5f, y2min = (bj.y - bj.w) * 0.5f;
        float x2max = (bj.x + bj.z) * 0.5f, y2max = (bj.y + bj.w) * 0.5f;
        float iw = fmaxf(fminf(x1max, x2max) - fmaxf(x1min, x2min), 0.f);
        float ih = fmaxf(fminf(y1max, y2max) - fmaxf(y1min, y2min), 0.f);
        float inter = iw * ih;
        float a1 = fabsf((x1max - x1min) * (y1max - y1min));
        float a2 = fabsf((x2max - x2min) * (y2max - y2min));
        float iou = inter / (a1 + a2 - inter + 1e-6f);
        sup = (iou >= 0.5f);
    }
    unsigned wmask = __ballot_sync(0xffffffffu, sup);
    if ((j & 31) == 0) {
        g_sup[i * 32 + (j >> 5)] = wmask;
        if (wmask) atomicOr(&s_any, 1u);
    }
    __syncthreads();
    if (j == 0 && s_any) atomicOr(&g_rowAny[i >> 5], 1u << (i & 31));
}

// ---------------------------------------------------------------- serial greedy reduce + output
__global__ void reduce_kernel(float* __restrict__ out) {
    __shared__ unsigned s_keep[32];
    int tid = threadIdx.x;
    if (tid < 32) {
        unsigned keepw = g_keep0[tid];
        unsigned anyw  = g_rowAny[tid];
        for (int w = 0; w < 32; w++) {
            unsigned aw = __shfl_sync(0xffffffffu, anyw,  w);
            unsigned kw = __shfl_sync(0xffffffffu, keepw, w);
            unsigned act = kw & aw;
            while (act) {
                int b = __ffs(act) - 1;              // lowest pending i in this word
                keepw &= ~g_sup[(w * 32 + b) * 32 + tid];
                kw = __shfl_sync(0xffffffffu, keepw, w);
                act = kw & aw & (0xFFFFFFFEu << b);  // only bits strictly > b remain
            }
        }
        s_keep[tid] = keepw;
    }
    __syncthreads();
    bool k = (s_keep[tid >> 5] >> (tid & 31)) & 1u;
    float4 b  = g_tb[tid];
    float cf  = g_tconf[tid];
    int   cl  = g_tcls[tid];
    float* o = out + (size_t)tid * 6;
    if (k) {
        o[0] = b.x; o[1] = b.y; o[2] = b.z; o[3] = b.w;
        o[4] = cf;  o[5] = (float)cl;
    } else {
        o[0] = 0.f; o[1] = 0.f; o[2] = 0.f; o[3] = 0.f; o[4] = 0.f; o[5] = 0.f;
    }
}

// ---------------------------------------------------------------- launch
extern "C" void kernel_launch(void* const* d_in, const int* in_sizes, int n_in,
                              void* d_out, int out_size) {
    const float* x       = (const float*)d_in[0];
    const float* anchors = (const float*)d_in[1];
    float* out = (float*)d_out;

    zero_kernel<<<256, 1024>>>();
    decode_kernel<<<dim3(169, 5), 256>>>(x, anchors);
    scan_kernel<<<1, 1024>>>();
    compact_kernel<<<(NBOX + 511) / 512, 512>>>();
    refine_kernel<<<32, 128>>>();
    sort_kernel<<<1, 1024>>>();
    matrix_kernel<<<KTOP, 1024>>>();
    reduce_kernel<<<1, 1024>>>(out);
}

// round 2
// speedup vs baseline: 1.2823x; 1.2823x over previous
#include <cuda_runtime.h>
#include <math.h>

#define AHW    43264          // 208*208
#define Q4     10816          // AHW/4
#define NBOX   216320         // 5*AHW
#define WGRID  208
#define NCLS   80
#define SHIFT  17
#define HB     16384          // buckets over p4 float bits >> 17
#define CAP    2048
#define KTOP   1024

__device__ __align__(16) unsigned g_hist[HB];
__device__ float               g_p4[NBOX];
__device__ float4              g_box[NBOX];
__device__ int                 g_cls[NBOX];
__device__ unsigned            g_T;
__device__ int                 g_count;
__device__ unsigned long long  g_keys[CAP];
__device__ float4              g_tb[KTOP];
__device__ float               g_tconf[KTOP];
__device__ int                 g_tcls[KTOP];
__device__ unsigned            g_keep0[32];
__device__ unsigned            g_rowAny[32];
__device__ unsigned            g_sup[KTOP * 32];

// ---------------------------------------------------------------- decode (float4)
// grid (43, 5) x 256 : t = float4 spatial idx, blockIdx.y = anchor
__global__ void decode_kernel(const float* __restrict__ x,
                              const float* __restrict__ anchors) {
    int t = blockIdx.x * 256 + threadIdx.x;
    if (t >= Q4) return;
    int a = blockIdx.y;
    const float4* px = (const float4*)(x + (size_t)a * (5 + NCLS) * AHW) + t;

    float4 p0 = __ldg(px);
    float4 p1 = __ldg(px + Q4);
    float4 p2 = __ldg(px + 2 * Q4);
    float4 p3 = __ldg(px + 3 * Q4);
    float4 p4 = __ldg(px + 4 * Q4);

    float4 best = __ldg(px + 5 * Q4);
    int b0 = 0, b1 = 0, b2 = 0, b3 = 0;
#pragma unroll 8
    for (int k = 1; k < NCLS; k++) {
        float4 v = __ldg(px + (5 + k) * Q4);
        if (v.x > best.x) { best.x = v.x; b0 = k; }
        if (v.y > best.y) { best.y = v.y; b1 = k; }
        if (v.z > best.z) { best.z = v.z; b2 = k; }
        if (v.w > best.w) { best.w = v.w; b3 = k; }
    }

    int h  = t / (WGRID / 4);                 // 52 float4 per row
    int w0 = (t - h * (WGRID / 4)) * 4;
    float aw = __ldg(&anchors[a * 2]);
    float ah = __ldg(&anchors[a * 2 + 1]);

    int n = a * AHW + t * 4;
    float hy = (float)h;

    float4 px0 = p0, py0 = p1;
    float bx0 = (1.f / (1.f + expf(-px0.x)) + (float)(w0 + 0)) * 32.f;
    float bx1 = (1.f / (1.f + expf(-px0.y)) + (float)(w0 + 1)) * 32.f;
    float bx2 = (1.f / (1.f + expf(-px0.z)) + (float)(w0 + 2)) * 32.f;
    float bx3 = (1.f / (1.f + expf(-px0.w)) + (float)(w0 + 3)) * 32.f;
    float by0 = (1.f / (1.f + expf(-py0.x)) + hy) * 32.f;
    float by1 = (1.f / (1.f + expf(-py0.y)) + hy) * 32.f;
    float by2 = (1.f / (1.f + expf(-py0.z)) + hy) * 32.f;
    float by3 = (1.f / (1.f + expf(-py0.w)) + hy) * 32.f;
    float aw32 = aw * 32.f, ah32 = ah * 32.f;

    g_box[n + 0] = make_float4(bx0, by0, expf(p2.x) * aw32, expf(p3.x) * ah32);
    g_box[n + 1] = make_float4(bx1, by1, expf(p2.y) * aw32, expf(p3.y) * ah32);
    g_box[n + 2] = make_float4(bx2, by2, expf(p2.z) * aw32, expf(p3.z) * ah32);
    g_box[n + 3] = make_float4(bx3, by3, expf(p2.w) * aw32, expf(p3.w) * ah32);
    *(int4*)&g_cls[n]   = make_int4(b0, b1, b2, b3);
    *(float4*)&g_p4[n]  = p4;

    if (p4.x > 0.f) atomicAdd(&g_hist[__float_as_uint(p4.x) >> SHIFT], 1u);
    if (p4.y > 0.f) atomicAdd(&g_hist[__float_as_uint(p4.y) >> SHIFT], 1u);
    if (p4.z > 0.f) atomicAdd(&g_hist[__float_as_uint(p4.z) >> SHIFT], 1u);
    if (p4.w > 0.f) atomicAdd(&g_hist[__float_as_uint(p4.w) >> SHIFT], 1u);
}

// ---------------------------------------------------------------- threshold select + zero scratch
__global__ void scan_kernel() {
    __shared__ unsigned partial[1024];
    __shared__ int s_sel[2];
    int t = threadIdx.x;
    // each thread owns a 16-bucket chunk
    const uint4* h4 = (const uint4*)g_hist;
    unsigned sum = 0;
    uint4 v0 = h4[t * 4 + 0], v1 = h4[t * 4 + 1], v2 = h4[t * 4 + 2], v3 = h4[t * 4 + 3];
    sum = v0.x + v0.y + v0.z + v0.w + v1.x + v1.y + v1.z + v1.w
        + v2.x + v2.y + v2.z + v2.w + v3.x + v3.y + v3.z + v3.w;
    partial[t] = sum;
    // zero candidate keys / counters while we're here
    g_keys[t] = 0ull; g_keys[t + 1024] = 0ull;
    if (t < 32) g_rowAny[t] = 0u;
    if (t == 0) g_count = 0;
    __syncthreads();
    if (t == 0) {
        unsigned acc = 0, before = 0; int c = -1;
        for (int q = 1023; q >= 0; q--) {
            before = acc; acc += partial[q];
            if (acc >= KTOP) { c = q; break; }
        }
        s_sel[0] = c; s_sel[1] = (int)before;
        if (c < 0) g_T = 0u;
    }
    __syncthreads();
    int c = s_sel[0];
    if (c < 0) return;
    if (t == 0) {
        unsigned acc = (unsigned)s_sel[1];
        int T = c * 16;
        for (int b = 15; b >= 0; b--) {
            acc += g_hist[c * 16 + b];
            if (acc >= KTOP) { T = c * 16 + b; break; }
        }
        T -= 2;                 // margin: covers fp32-sigmoid ties at the cutoff
        if (T < 0) T = 0;
        g_T = (unsigned)T;
    }
}

// ---------------------------------------------------------------- compact + exact key (fp64 sigmoid)
__global__ void compact_kernel() {
    int t = blockIdx.x * 256 + threadIdx.x;
    if (t >= NBOX / 4) return;
    float4 p = ((const float4*)g_p4)[t];
    unsigned T = g_T;
    float pv[4] = {p.x, p.y, p.z, p.w};
#pragma unroll
    for (int c = 0; c < 4; c++) {
        float v = pv[c];
        if (v > 0.f && (__float_as_uint(v) >> SHIFT) >= T) {
            int pos = atomicAdd(&g_count, 1);
            if (pos < CAP) {
                unsigned idx = (unsigned)(t * 4 + c);
                double e = exp(-(double)v);
                float conf = (float)(1.0 / (1.0 + e));
                g_keys[pos] = ((unsigned long long)__float_as_uint(conf) << 32)
                              | (unsigned)(~idx);
            }
        }
    }
}

// ---------------------------------------------------------------- bitonic sort 2048 (desc) + emit top arrays
__global__ void sort_kernel() {
    __shared__ unsigned long long sk[CAP];
    int tid = threadIdx.x;
    sk[tid] = g_keys[tid];
    sk[tid + 1024] = g_keys[tid + 1024];
    __syncthreads();

    for (int k = 2; k <= CAP; k <<= 1) {
        for (int j = k >> 1; j > 0; j >>= 1) {
#pragma unroll
            for (int m = 0; m < 2; m++) {
                int t = tid + m * 1024;
                int ixj = t ^ j;
                if (ixj > t) {
                    unsigned long long a = sk[t], b = sk[ixj];
                    bool descSeg = ((t & k) == 0);
                    if (descSeg ? (a < b) : (a > b)) { sk[t] = b; sk[ixj] = a; }
                }
            }
            __syncthreads();
        }
    }

    unsigned long long key = sk[tid];
    bool valid = (key != 0ull);
    float4 b4 = make_float4(0.f, 0.f, 0.f, 0.f);
    int cl = 0; float conf = 0.f;
    if (valid) {
        unsigned idx = ~(unsigned)(key & 0xFFFFFFFFull);
        b4   = g_box[idx];
        cl   = g_cls[idx];
        conf = __uint_as_float((unsigned)(key >> 32));
    }
    g_tb[tid]    = b4;
    g_tcls[tid]  = cl;
    g_tconf[tid] = conf;
    unsigned wmask = __ballot_sync(0xffffffffu, valid);
    if ((tid & 31) == 0) g_keep0[tid >> 5] = wmask;
}

// ---------------------------------------------------------------- suppression matrix (tiled: 32 rows/block)
__global__ void matrix_kernel() {
    __shared__ float4 sb[KTOP];
    __shared__ int    scl[KTOP];
    __shared__ unsigned s_blockAny;
    int j = threadIdx.x;
    sb[j]  = g_tb[j];
    scl[j] = g_tcls[j];
    if (j == 0) s_blockAny = 0u;
    __syncthreads();

    int w    = j >> 5;                 // warp = row within tile
    int lane = j & 31;
    int i    = blockIdx.x * 32 + w;
    float4 bi = sb[i];
    int   cli = scl[i];
    float x1min = (bi.x - bi.z) * 0.5f, y1min = (bi.y - bi.w) * 0.5f;
    float x1max = (bi.x + bi.z) * 0.5f, y1max = (bi.y + bi.w) * 0.5f;
    float a1 = fabsf((x1max - x1min) * (y1max - y1min));

    unsigned anyw = 0u;
#pragma unroll 4
    for (int c = 0; c < 32; c++) {
        int jj = c * 32 + lane;
        float4 bj = sb[jj];
        bool sup = false;
        if (jj > i && scl[jj] == cli) {
            float x2min = (bj.x - bj.z) * 0.5f, y2min = (bj.y - bj.w) * 0.5f;
            float x2max = (bj.x + bj.z) * 0.5f, y2max = (bj.y + bj.w) * 0.5f;
            float iw = fmaxf(fminf(x1max, x2max) - fmaxf(x1min, x2min), 0.f);
            float ih = fmaxf(fminf(y1max, y2max) - fmaxf(y1min, y2min), 0.f);
            float inter = iw * ih;
            float a2 = fabsf((x2max - x2min) * (y2max - y2min));
            float iou = inter / (a1 + a2 - inter + 1e-6f);
            sup = (iou >= 0.5f);
        }
        unsigned wmask = __ballot_sync(0xffffffffu, sup);
        if (lane == 0) g_sup[i * 32 + c] = wmask;
        anyw |= wmask;
    }
    if (lane == 0 && anyw) atomicOr(&s_blockAny, 1u << w);
    __syncthreads();
    if (j == 0) g_rowAny[blockIdx.x] = s_blockAny;
}

// ---------------------------------------------------------------- serial greedy reduce + output + re-zero hist
__global__ void reduce_kernel(float* __restrict__ out) {
    __shared__ unsigned s_keep[32];
    int tid = threadIdx.x;
    if (tid < 32) {
        unsigned keepw = g_keep0[tid];
        unsigned anyw  = g_rowAny[tid];
        for (int w = 0; w < 32; w++) {
            unsigned aw = __shfl_sync(0xffffffffu, anyw,  w);
            unsigned kw = __shfl_sync(0xffffffffu, keepw, w);
            unsigned act = kw & aw;
            while (act) {
                int b = __ffs(act) - 1;
                keepw &= ~g_sup[(w * 32 + b) * 32 + tid];
                kw = __shfl_sync(0xffffffffu, keepw, w);
                act = kw & aw & (0xFFFFFFFEu << b);
            }
        }
        s_keep[tid] = keepw;
    }
    __syncthreads();
    bool k = (s_keep[tid >> 5] >> (tid & 31)) & 1u;
    float4 b  = g_tb[tid];
    float cf  = g_tconf[tid];
    int   cl  = g_tcls[tid];
    float* o = out + (size_t)tid * 6;
    if (k) {
        o[0] = b.x; o[1] = b.y; o[2] = b.z; o[3] = b.w;
        o[4] = cf;  o[5] = (float)cl;
    } else {
        o[0] = 0.f; o[1] = 0.f; o[2] = 0.f; o[3] = 0.f; o[4] = 0.f; o[5] = 0.f;
    }
    // re-zero histogram for the next graph replay (globals are zero-init at
    // module load, so the very first execution is also clean)
    uint4 z = make_uint4(0u, 0u, 0u, 0u);
    uint4* h4 = (uint4*)g_hist;
#pragma unroll
    for (int q = 0; q < 4; q++) h4[tid + q * 1024] = z;
}

// ---------------------------------------------------------------- launch
extern "C" void kernel_launch(void* const* d_in, const int* in_sizes, int n_in,
                              void* d_out, int out_size) {
    const float* x       = (const float*)d_in[0];
    const float* anchors = (const float*)d_in[1];
    float* out = (float*)d_out;

    decode_kernel<<<dim3(43, 5), 256>>>(x, anchors);
    scan_kernel<<<1, 1024>>>();
    compact_kernel<<<(NBOX / 4 + 255) / 256, 256>>>();
    sort_kernel<<<1, 1024>>>();
    matrix_kernel<<<KTOP / 32, 1024>>>();
    reduce_kernel<<<1, 1024>>>(out);
}

// round 3
// speedup vs baseline: 1.4277x; 1.1133x over previous
#include <cuda_runtime.h>
#include <math.h>

#define AHW    43264          // 208*208
#define Q4     10816          // AHW/4
#define NBOX   216320
#define NB4    54080          // 5*Q4 conf float4s
#define WGRID  208
#define NCLS   80
#define SHIFT  17
#define HB     16384          // buckets over p4 float bits >> 17
#define CAP    2048
#define KTOP   1024

__device__ __align__(16) unsigned g_hist[HB];
__device__ unsigned long long  g_keys[CAP];
__device__ int                 g_count;
__device__ unsigned            g_arrB;
__device__ unsigned            g_arrD;
__device__ float4              g_tb[KTOP];
__device__ float               g_tconf[KTOP];
__device__ int                 g_tcls[KTOP];
__device__ unsigned            g_keep0[32];
__device__ unsigned            g_rowAny[32];
__device__ unsigned            g_sup[KTOP * 32];

// ---------------------------------------------------------------- A: conf histogram
// reads ONLY the 5 objectness channels (0.87 MB)
__global__ void hist_kernel(const float* __restrict__ x) {
    int t = blockIdx.x * 256 + threadIdx.x;
    if (t >= Q4) return;
    int a = blockIdx.y;
    const float4* p = (const float4*)(x + (size_t)(a * 85 + 4) * AHW) + t;
    float4 v = __ldg(p);
    if (v.x > 0.f) atomicAdd(&g_hist[__float_as_uint(v.x) >> SHIFT], 1u);
    if (v.y > 0.f) atomicAdd(&g_hist[__float_as_uint(v.y) >> SHIFT], 1u);
    if (v.z > 0.f) atomicAdd(&g_hist[__float_as_uint(v.z) >> SHIFT], 1u);
    if (v.w > 0.f) atomicAdd(&g_hist[__float_as_uint(v.w) >> SHIFT], 1u);
}

// ---------------------------------------------------------------- B: threshold + compact + (last block) sort
__global__ void __launch_bounds__(1024) compact_sort_kernel(const float* __restrict__ x) {
    __shared__ unsigned suf[1024];
    __shared__ int s_c;
    __shared__ unsigned s_T;
    __shared__ bool s_last;
    __shared__ unsigned long long sk[CAP];

    int tid = threadIdx.x;

    // --- redundant per-block threshold: parallel suffix scan over 1024 16-bucket chunks
    const uint4* h4 = (const uint4*)g_hist;
    uint4 a0 = h4[tid * 4 + 0], a1 = h4[tid * 4 + 1], a2 = h4[tid * 4 + 2], a3 = h4[tid * 4 + 3];
    suf[tid] = a0.x + a0.y + a0.z + a0.w + a1.x + a1.y + a1.z + a1.w
             + a2.x + a2.y + a2.z + a2.w + a3.x + a3.y + a3.z + a3.w;
    if (tid == 0) s_c = -1;
    __syncthreads();
    for (int d = 1; d < 1024; d <<= 1) {
        unsigned v = (tid + d < 1024) ? suf[tid + d] : 0u;
        __syncthreads();
        suf[tid] += v;
        __syncthreads();
    }
    unsigned mine = suf[tid];
    unsigned nxt = (tid < 1023) ? suf[tid + 1] : 0u;
    if (mine >= KTOP && nxt < KTOP) s_c = tid;         // unique (suffix monotone)
    __syncthreads();
    if (tid == 0) {
        int c = s_c;
        if (c < 0) s_T = 0u;
        else {
            unsigned acc = (c < 1023) ? suf[c + 1] : 0u;
            int T = c * 16;
            for (int b = 15; b >= 0; b--) {
                acc += g_hist[c * 16 + b];
                if (acc >= KTOP) { T = c * 16 + b; break; }
            }
            T -= 2;                                     // tie-safety margin
            if (T < 0) T = 0;
            s_T = (unsigned)T;
        }
    }
    __syncthreads();
    unsigned T = s_T;

    // --- compaction: re-read conf channels (hot in L2), exact fp64 sigmoid keys
    int t = blockIdx.x * 1024 + tid;
    if (t < NB4) {
        int a = t / Q4;
        int q = t - a * Q4;
        float4 p = __ldg((const float4*)(x + (size_t)(a * 85 + 4) * AHW) + q);
        float pv[4] = {p.x, p.y, p.z, p.w};
#pragma unroll
        for (int c = 0; c < 4; c++) {
            float v = pv[c];
            if (v > 0.f && (__float_as_uint(v) >> SHIFT) >= T) {
                int pos = atomicAdd(&g_count, 1);
                if (pos < CAP) {
                    unsigned idx = (unsigned)(a * AHW + q * 4 + c);
                    double e = exp(-(double)v);
                    float conf = (float)(1.0 / (1.0 + e));
                    g_keys[pos] = ((unsigned long long)__float_as_uint(conf) << 32)
                                  | (unsigned)(~idx);
                }
            }
        }
    }

    // --- last-block handoff
    __threadfence();
    __syncthreads();
    if (tid == 0) s_last = (atomicAdd(&g_arrB, 1u) == gridDim.x - 1);
    __syncthreads();
    if (!s_last) return;

    // --- hybrid bitonic sort of 2048 keys (descending), 2 elems/thread
    unsigned long long r0 = __ldcg(&g_keys[tid]);
    unsigned long long r1 = __ldcg(&g_keys[tid + 1024]);
    int lane = tid & 31;

    for (int k = 2; k <= CAP; k <<= 1) {
        for (int j = k >> 1; j > 0; j >>= 1) {
            if (j == 1024) {
                // in-thread pair (e0=tid desc-keeps-max)
                unsigned long long mx = r0 > r1 ? r0 : r1;
                unsigned long long mn = r0 > r1 ? r1 : r0;
                r0 = mx; r1 = mn;
            } else if (j >= 32) {
                sk[tid] = r0; sk[tid + 1024] = r1;
                __syncthreads();
                unsigned long long b0 = sk[tid ^ j];
                unsigned long long b1 = sk[(tid ^ j) + 1024];
                bool lower = ((tid & j) == 0);
                bool d0 = ((tid & k) == 0);
                bool d1 = (((tid + 1024) & k) == 0);
                bool km0 = (lower == d0), km1 = (lower == d1);
                r0 = km0 ? (r0 > b0 ? r0 : b0) : (r0 < b0 ? r0 : b0);
                r1 = km1 ? (r1 > b1 ? r1 : b1) : (r1 < b1 ? r1 : b1);
                __syncthreads();
            } else {
                unsigned long long b0 = __shfl_xor_sync(0xffffffffu, r0, j);
                unsigned long long b1 = __shfl_xor_sync(0xffffffffu, r1, j);
                bool lower = ((lane & j) == 0);
                bool d0 = ((tid & k) == 0);
                bool d1 = (((tid + 1024) & k) == 0);
                bool km0 = (lower == d0), km1 = (lower == d1);
                r0 = km0 ? (r0 > b0 ? r0 : b0) : (r0 < b0 ? r0 : b0);
                r1 = km1 ? (r1 > b1 ? r1 : b1) : (r1 < b1 ? r1 : b1);
            }
        }
    }

    g_keys[tid] = r0;            // rank tid
    g_keys[tid + 1024] = r1;     // ranks >= 1024 (unused; zeroed by emit)
    bool valid = (r0 != 0ull);
    unsigned wm = __ballot_sync(0xffffffffu, valid);
    if (lane == 0) g_keep0[tid >> 5] = wm;
    if (tid == 0) { g_count = 0; g_arrB = 0u; }
}

// ---------------------------------------------------------------- C: gather-decode top-1024 only
__global__ void emit_kernel(const float* __restrict__ x,
                            const float* __restrict__ anchors) {
    int r = blockIdx.x * 256 + threadIdx.x;      // rank 0..1023
    unsigned long long key = g_keys[r];
    // zero keys for next replay (each thread owns rank r and r+1024)
    g_keys[r] = 0ull; g_keys[r + 1024] = 0ull;

    float4 b4 = make_float4(0.f, 0.f, 0.f, 0.f);
    int cl = 0; float conf = 0.f;
    if (key != 0ull) {
        unsigned idx = ~(unsigned)(key & 0xFFFFFFFFull);
        conf = __uint_as_float((unsigned)(key >> 32));
        int a = idx / AHW;
        int s = idx - a * AHW;
        int h = s / WGRID;
        int w = s - h * WGRID;
        const float* px = x + (size_t)(a * 85) * AHW + s;
        float p0 = __ldg(px);
        float p1 = __ldg(px + AHW);
        float p2 = __ldg(px + 2 * (size_t)AHW);
        float p3 = __ldg(px + 3 * (size_t)AHW);
        const float* pc = px + 5 * (size_t)AHW;
        float best = __ldg(pc);
        int bi = 0;
#pragma unroll 8
        for (int k = 1; k < NCLS; k++) {
            float v = __ldg(pc + (size_t)k * AHW);
            if (v > best) { best = v; bi = k; }
        }
        float aw = __ldg(&anchors[a * 2]);
        float ah = __ldg(&anchors[a * 2 + 1]);
        float bx = (1.f / (1.f + expf(-p0)) + (float)w) * 32.f;
        float by = (1.f / (1.f + expf(-p1)) + (float)h) * 32.f;
        b4 = make_float4(bx, by, expf(p2) * aw * 32.f, expf(p3) * ah * 32.f);
        cl = bi;
    }
    g_tb[r]    = b4;
    g_tcls[r]  = cl;
    g_tconf[r] = conf;
}

// ---------------------------------------------------------------- D: suppression matrix + (last block) greedy reduce
__global__ void __launch_bounds__(1024) matrix_reduce_kernel(float* __restrict__ out) {
    __shared__ float4 sb[KTOP];
    __shared__ int    scl[KTOP];
    __shared__ unsigned s_blockAny;
    __shared__ bool s_last;
    __shared__ unsigned s_keep[32];
    int j = threadIdx.x;
    sb[j]  = g_tb[j];
    scl[j] = g_tcls[j];
    if (j == 0) s_blockAny = 0u;
    __syncthreads();

    int w    = j >> 5;
    int lane = j & 31;
    int i    = blockIdx.x * 32 + w;
    float4 bi = sb[i];
    int   cli = scl[i];
    float x1min = (bi.x - bi.z) * 0.5f, y1min = (bi.y - bi.w) * 0.5f;
    float x1max = (bi.x + bi.z) * 0.5f, y1max = (bi.y + bi.w) * 0.5f;
    float a1 = fabsf((x1max - x1min) * (y1max - y1min));

    unsigned anyw = 0u;
#pragma unroll 4
    for (int c = 0; c < 32; c++) {
        int jj = c * 32 + lane;
        float4 bj = sb[jj];
        bool sup = false;
        if (jj > i && scl[jj] == cli) {
            float x2min = (bj.x - bj.z) * 0.5f, y2min = (bj.y - bj.w) * 0.5f;
            float x2max = (bj.x + bj.z) * 0.5f, y2max = (bj.y + bj.w) * 0.5f;
            float iw = fmaxf(fminf(x1max, x2max) - fmaxf(x1min, x2min), 0.f);
            float ih = fmaxf(fminf(y1max, y2max) - fmaxf(y1min, y2min), 0.f);
            float inter = iw * ih;
            float a2 = fabsf((x2max - x2min) * (y2max - y2min));
            float iou = inter / (a1 + a2 - inter + 1e-6f);
            sup = (iou >= 0.5f);
        }
        unsigned wmask = __ballot_sync(0xffffffffu, sup);
        if (lane == 0) g_sup[i * 32 + c] = wmask;
        anyw |= wmask;
    }
    if (lane == 0 && anyw) atomicOr(&s_blockAny, 1u << w);
    __syncthreads();
    if (j == 0) g_rowAny[blockIdx.x] = s_blockAny;

    // last-block handoff
    __threadfence();
    __syncthreads();
    if (j == 0) s_last = (atomicAdd(&g_arrD, 1u) == gridDim.x - 1);
    __syncthreads();
    if (!s_last) return;

    // greedy serial bit-sweep (one warp), peer-block data via __ldcg
    int tid = j;
    if (tid < 32) {
        unsigned keepw = g_keep0[tid];
        unsigned anyv  = __ldcg(&g_rowAny[tid]);
        for (int ww = 0; ww < 32; ww++) {
            unsigned aw = __shfl_sync(0xffffffffu, anyv,  ww);
            unsigned kw = __shfl_sync(0xffffffffu, keepw, ww);
            unsigned act = kw & aw;
            while (act) {
                int b = __ffs(act) - 1;
                keepw &= ~__ldcg(&g_sup[(ww * 32 + b) * 32 + tid]);
                kw = __shfl_sync(0xffffffffu, keepw, ww);
                act = kw & aw & (0xFFFFFFFEu << b);
            }
        }
        s_keep[tid] = keepw;
    }
    __syncthreads();
    bool k = (s_keep[tid >> 5] >> (tid & 31)) & 1u;
    float4 b  = sb[tid];
    float cf  = g_tconf[tid];
    int   cl  = scl[tid];
    float* o = out + (size_t)tid * 6;
    if (k) {
        o[0] = b.x; o[1] = b.y; o[2] = b.z; o[3] = b.w;
        o[4] = cf;  o[5] = (float)cl;
    } else {
        o[0] = 0.f; o[1] = 0.f; o[2] = 0.f; o[3] = 0.f; o[4] = 0.f; o[5] = 0.f;
    }
    // re-zero histogram + counters for next replay
    uint4 z = make_uint4(0u, 0u, 0u, 0u);
    uint4* h4 = (uint4*)g_hist;
#pragma unroll
    for (int q = 0; q < 4; q++) h4[tid + q * 1024] = z;
    if (tid == 0) g_arrD = 0u;
}

// ---------------------------------------------------------------- launch
extern "C" void kernel_launch(void* const* d_in, const int* in_sizes, int n_in,
                              void* d_out, int out_size) {
    const float* x       = (const float*)d_in[0];
    const float* anchors = (const float*)d_in[1];
    float* out = (float*)d_out;

    hist_kernel<<<dim3(43, 5), 256>>>(x);
    compact_sort_kernel<<<53, 1024>>>(x);
    emit_kernel<<<4, 256>>>(x, anchors);
    matrix_reduce_kernel<<<32, 1024>>>(out);
}

// round 4
// speedup vs baseline: 1.5116x; 1.0588x over previous
#include <cuda_runtime.h>
#include <math.h>

#define AHW    43264          // 208*208
#define Q4     10816          // AHW/4
#define NB4    54080          // 5*Q4 conf float4s
#define WGRID  208
#define NCLS   80
#define SHIFT  17
#define HB     16384          // buckets over p4 float bits >> 17
#define CAP    2048
#define KTOP   1024
#define GRID1  53
#define GRID2  32

__device__ __align__(16) unsigned g_hist[HB];
__device__ unsigned long long  g_keys[CAP];
__device__ int                 g_count;
__device__ unsigned            g_sync1, g_sync2, g_sync3, g_sync4;
__device__ float4              g_tb[KTOP];
__device__ float               g_tconf[KTOP];
__device__ int                 g_tcls[KTOP];
__device__ unsigned            g_keep0[32];
__device__ unsigned            g_rowAny[32];
__device__ unsigned            g_sup[KTOP * 32];

// ================================================================ kernel 1
// hist -> gridsync -> threshold+compact -> gridsync -> (last block) sort
__global__ void __launch_bounds__(1024) select_kernel(const float* __restrict__ x) {
    __shared__ unsigned suf[1024];
    __shared__ int s_c;
    __shared__ unsigned s_T;
    __shared__ bool s_last;
    __shared__ unsigned long long sk[CAP];

    int tid = threadIdx.x;
    int t = blockIdx.x * 1024 + tid;

    // ---- phase A: histogram of conf-logit bits (keeps the float4 in regs)
    float4 p = make_float4(-1.f, -1.f, -1.f, -1.f);
    int a = 0, q = 0;
    if (t < NB4) {
        a = t / Q4;
        q = t - a * Q4;
        p = __ldg((const float4*)(x + (size_t)(a * 85 + 4) * AHW) + q);
        if (p.x > 0.f) atomicAdd(&g_hist[__float_as_uint(p.x) >> SHIFT], 1u);
        if (p.y > 0.f) atomicAdd(&g_hist[__float_as_uint(p.y) >> SHIFT], 1u);
        if (p.z > 0.f) atomicAdd(&g_hist[__float_as_uint(p.z) >> SHIFT], 1u);
        if (p.w > 0.f) atomicAdd(&g_hist[__float_as_uint(p.w) >> SHIFT], 1u);
    }

    // ---- grid sync 1 (all GRID1 blocks resident)
    __threadfence();
    __syncthreads();
    if (tid == 0) {
        atomicAdd(&g_sync1, 1u);
        while (*(volatile unsigned*)&g_sync1 < GRID1) __nanosleep(64);
    }
    __syncthreads();
    __threadfence();

    // ---- phase B: per-block parallel threshold (suffix scan over 1024 chunks)
    const uint4* h4 = (const uint4*)g_hist;
    uint4 a0 = h4[tid * 4 + 0], a1 = h4[tid * 4 + 1], a2 = h4[tid * 4 + 2], a3 = h4[tid * 4 + 3];
    suf[tid] = a0.x + a0.y + a0.z + a0.w + a1.x + a1.y + a1.z + a1.w
             + a2.x + a2.y + a2.z + a2.w + a3.x + a3.y + a3.z + a3.w;
    if (tid == 0) s_c = -1;
    __syncthreads();
    for (int d = 1; d < 1024; d <<= 1) {
        unsigned v = (tid + d < 1024) ? suf[tid + d] : 0u;
        __syncthreads();
        suf[tid] += v;
        __syncthreads();
    }
    {
        unsigned mine = suf[tid];
        unsigned nxt = (tid < 1023) ? suf[tid + 1] : 0u;
        if (mine >= KTOP && nxt < KTOP) s_c = tid;
    }
    __syncthreads();
    if (tid == 0) {
        int c = s_c;
        if (c < 0) s_T = 0u;
        else {
            unsigned acc = (c < 1023) ? suf[c + 1] : 0u;
            int T = c * 16;
            for (int b = 15; b >= 0; b--) {
                acc += g_hist[c * 16 + b];
                if (acc >= KTOP) { T = c * 16 + b; break; }
            }
            T -= 2;                                  // tie-safety margin
            if (T < 0) T = 0;
            s_T = (unsigned)T;
        }
    }
    __syncthreads();
    unsigned T = s_T;

    // ---- compact with exact fp64-sigmoid keys (float4 still in regs)
    if (t < NB4) {
        float pv[4] = {p.x, p.y, p.z, p.w};
#pragma unroll
        for (int c = 0; c < 4; c++) {
            float v = pv[c];
            if (v > 0.f && (__float_as_uint(v) >> SHIFT) >= T) {
                int pos = atomicAdd(&g_count, 1);
                if (pos < CAP) {
                    unsigned idx = (unsigned)(a * AHW + q * 4 + c);
                    double e = exp(-(double)v);
                    float conf = (float)(1.0 / (1.0 + e));
                    g_keys[pos] = ((unsigned long long)__float_as_uint(conf) << 32)
                                  | (unsigned)(~idx);
                }
            }
        }
    }

    // ---- grid sync 2: last block proceeds to sort
    __threadfence();
    __syncthreads();
    if (tid == 0) s_last = (atomicAdd(&g_sync2, 1u) == GRID1 - 1);
    __syncthreads();
    if (!s_last) return;
    __threadfence();

    // ---- hybrid bitonic sort of 2048 keys (descending), 2 per thread
    unsigned long long r0 = __ldcg(&g_keys[tid]);
    unsigned long long r1 = __ldcg(&g_keys[tid + 1024]);
    int lane = tid & 31;

    for (int k = 2; k <= CAP; k <<= 1) {
        for (int j = k >> 1; j > 0; j >>= 1) {
            if (j == 1024) {
                unsigned long long mx = r0 > r1 ? r0 : r1;
                unsigned long long mn = r0 > r1 ? r1 : r0;
                r0 = mx; r1 = mn;
            } else if (j >= 32) {
                sk[tid] = r0; sk[tid + 1024] = r1;
                __syncthreads();
                unsigned long long b0 = sk[tid ^ j];
                unsigned long long b1 = sk[(tid ^ j) + 1024];
                bool lower = ((tid & j) == 0);
                bool d0 = ((tid & k) == 0);
                bool d1 = (((tid + 1024) & k) == 0);
                bool km0 = (lower == d0), km1 = (lower == d1);
                r0 = km0 ? (r0 > b0 ? r0 : b0) : (r0 < b0 ? r0 : b0);
                r1 = km1 ? (r1 > b1 ? r1 : b1) : (r1 < b1 ? r1 : b1);
                __syncthreads();
            } else {
                unsigned long long b0 = __shfl_xor_sync(0xffffffffu, r0, j);
                unsigned long long b1 = __shfl_xor_sync(0xffffffffu, r1, j);
                bool lower = ((lane & j) == 0);
                bool d0 = ((tid & k) == 0);
                bool d1 = (((tid + 1024) & k) == 0);
                bool km0 = (lower == d0), km1 = (lower == d1);
                r0 = km0 ? (r0 > b0 ? r0 : b0) : (r0 < b0 ? r0 : b0);
                r1 = km1 ? (r1 > b1 ? r1 : b1) : (r1 < b1 ? r1 : b1);
            }
        }
    }

    g_keys[tid] = r0;            // rank tid (top-1024)
    g_keys[tid + 1024] = 0ull;   // pre-zero upper half for next replay
    bool valid = (r0 != 0ull);
    unsigned wm = __ballot_sync(0xffffffffu, valid);
    if (lane == 0) g_keep0[tid >> 5] = wm;
    if (tid == 0) { g_count = 0; g_sync1 = 0u; g_sync2 = 0u; }
}

// ================================================================ kernel 2
// emit(warp/rank) -> gridsync -> matrix -> (last block) smem-cached sweep + out
extern __shared__ unsigned char dynsmem[];

__global__ void __launch_bounds__(1024) nms_kernel(const float* __restrict__ x,
                                                   const float* __restrict__ anchors,
                                                   float* __restrict__ out) {
    unsigned* rows = (unsigned*)dynsmem;                       // 128 KB
    float4*   sb   = (float4*)(dynsmem + KTOP * 32 * 4);       // 16 KB
    int*      scl  = (int*)(dynsmem + KTOP * 32 * 4 + KTOP * 16); // 4 KB
    __shared__ unsigned s_blockAny;
    __shared__ bool s_last;
    __shared__ unsigned s_keep[32];
    __shared__ unsigned s_any[32];

    int tid  = threadIdx.x;
    int wid  = tid >> 5;
    int lane = tid & 31;

    // ---- phase E: gather-decode top-1024, one warp per rank
    {
        int r = blockIdx.x * 32 + wid;
        unsigned long long key = 0ull;
        if (lane == 0) key = g_keys[r];
        key = __shfl_sync(0xffffffffu, key, 0);

        float4 b4 = make_float4(0.f, 0.f, 0.f, 0.f);
        int cl = 0; float conf = 0.f;
        if (key != 0ull) {
            unsigned idx = ~(unsigned)(key & 0xFFFFFFFFull);
            conf = __uint_as_float((unsigned)(key >> 32));
            int a = idx / AHW;
            int s = idx - a * AHW;
            const float* px = x + (size_t)(a * 85) * AHW + s;
            // distributed class argmax: lane handles k = lane, lane+32, lane+64
            const float* pc = px + 5 * (size_t)AHW;
            float bv = -3.4e38f; int bi = NCLS;
#pragma unroll
            for (int m = 0; m < 3; m++) {
                int k = lane + 32 * m;
                if (k < NCLS) {
                    float v = __ldg(pc + (size_t)k * AHW);
                    if (v > bv || (v == bv && k < bi)) { bv = v; bi = k; }
                }
            }
#pragma unroll
            for (int off = 16; off > 0; off >>= 1) {
                float ov = __shfl_xor_sync(0xffffffffu, bv, off);
                int   oi = __shfl_xor_sync(0xffffffffu, bi, off);
                if (ov > bv || (ov == bv && oi < bi)) { bv = ov; bi = oi; }
            }
            cl = bi;
            if (lane == 0) {
                int h = s / WGRID;
                int w = s - h * WGRID;
                float p0 = __ldg(px);
                float p1 = __ldg(px + AHW);
                float p2 = __ldg(px + 2 * (size_t)AHW);
                float p3 = __ldg(px + 3 * (size_t)AHW);
                float aw = __ldg(&anchors[a * 2]);
                float ah = __ldg(&anchors[a * 2 + 1]);
                float bx = (1.f / (1.f + expf(-p0)) + (float)w) * 32.f;
                float by = (1.f / (1.f + expf(-p1)) + (float)h) * 32.f;
                b4 = make_float4(bx, by, expf(p2) * aw * 32.f, expf(p3) * ah * 32.f);
            }
        }
        if (lane == 0) {
            g_tb[r]    = b4;
            g_tcls[r]  = cl;
            g_tconf[r] = conf;
            g_keys[r]  = 0ull;         // pre-zero lower half for next replay
        }
    }

    // ---- grid sync 3 (32 blocks resident)
    __threadfence();
    __syncthreads();
    if (tid == 0) {
        atomicAdd(&g_sync3, 1u);
        while (*(volatile unsigned*)&g_sync3 < GRID2) __nanosleep(64);
    }
    __syncthreads();
    __threadfence();

    // ---- phase M: suppression matrix, 32 rows per block
    sb[tid]  = __ldcg((const float4*)&g_tb[tid]);
    scl[tid] = __ldcg(&g_tcls[tid]);
    if (tid == 0) s_blockAny = 0u;
    __syncthreads();

    {
        int i = blockIdx.x * 32 + wid;
        float4 bi = sb[i];
        int   cli = scl[i];
        float x1min = (bi.x - bi.z) * 0.5f, y1min = (bi.y - bi.w) * 0.5f;
        float x1max = (bi.x + bi.z) * 0.5f, y1max = (bi.y + bi.w) * 0.5f;
        float a1 = fabsf((x1max - x1min) * (y1max - y1min));

        unsigned anyw = 0u;
#pragma unroll 4
        for (int c = 0; c < 32; c++) {
            int jj = c * 32 + lane;
            float4 bj = sb[jj];
            bool sup = false;
            if (jj > i && scl[jj] == cli) {
                float x2min = (bj.x - bj.z) * 0.5f, y2min = (bj.y - bj.w) * 0.5f;
                float x2max = (bj.x + bj.z) * 0.5f, y2max = (bj.y + bj.w) * 0.5f;
                float iw = fmaxf(fminf(x1max, x2max) - fmaxf(x1min, x2min), 0.f);
                float ih = fmaxf(fminf(y1max, y2max) - fmaxf(y1min, y2min), 0.f);
                float inter = iw * ih;
                float a2 = fabsf((x2max - x2min) * (y2max - y2min));
                float iou = inter / (a1 + a2 - inter + 1e-6f);
                sup = (iou >= 0.5f);
            }
            unsigned wmask = __ballot_sync(0xffffffffu, sup);
            if (lane == 0) g_sup[i * 32 + c] = wmask;
            anyw |= wmask;
        }
        if (lane == 0 && anyw) atomicOr(&s_blockAny, 1u << wid);
    }
    __syncthreads();
    if (tid == 0) g_rowAny[blockIdx.x] = s_blockAny;

    // ---- grid sync 4: last block does the reduce
    __threadfence();
    __syncthreads();
    if (tid == 0) s_last = (atomicAdd(&g_sync4, 1u) == GRID2 - 1);
    __syncthreads();
    if (!s_last) return;
    __threadfence();

    // ---- phase R: cache active suppression rows in shared, then sweep
    if (tid < 32) s_any[tid] = __ldcg(&g_rowAny[tid]);
    __syncthreads();
    for (int i = wid; i < KTOP; i += 32) {
        if ((s_any[i >> 5] >> (i & 31)) & 1u)
            rows[i * 32 + lane] = __ldcg(&g_sup[i * 32 + lane]);
    }
    __syncthreads();

    if (tid < 32) {
        unsigned keepw = __ldcg(&g_keep0[tid]);
        unsigned anyv  = s_any[tid];
        for (int ww = 0; ww < 32; ww++) {
            unsigned aw = __shfl_sync(0xffffffffu, anyv,  ww);
            unsigned kw = __shfl_sync(0xffffffffu, keepw, ww);
            unsigned act = kw & aw;
            while (act) {
                int b = __ffs(act) - 1;
                keepw &= ~rows[(ww * 32 + b) * 32 + tid];
                kw = __shfl_sync(0xffffffffu, keepw, ww);
                act = kw & aw & (0xFFFFFFFEu << b);
            }
        }
        s_keep[tid] = keepw;
    }
    __syncthreads();

    // ---- output + state re-zero for next replay
    {
        bool k = (s_keep[tid >> 5] >> (tid & 31)) & 1u;
        float4 b  = sb[tid];
        float cf  = __ldcg(&g_tconf[tid]);
        int   cl  = scl[tid];
        float* o = out + (size_t)tid * 6;
        if (k) {
            o[0] = b.x; o[1] = b.y; o[2] = b.z; o[3] = b.w;
            o[4] = cf;  o[5] = (float)cl;
        } else {
            o[0] = 0.f; o[1] = 0.f; o[2] = 0.f; o[3] = 0.f; o[4] = 0.f; o[5] = 0.f;
        }
    }
    {
        uint4 z = make_uint4(0u, 0u, 0u, 0u);
        uint4* h4 = (uint4*)g_hist;
#pragma unroll
        for (int qq = 0; qq < 4; qq++) h4[tid + qq * 1024] = z;
    }
    if (tid == 0) { g_sync3 = 0u; g_sync4 = 0u; }
}

// ---------------------------------------------------------------- launch
extern "C" void kernel_launch(void* const* d_in, const int* in_sizes, int n_in,
                              void* d_out, int out_size) {
    const float* x       = (const float*)d_in[0];
    const float* anchors = (const float*)d_in[1];
    float* out = (float*)d_out;

    static bool s_attr = false;
    const int SMEM2 = KTOP * 32 * 4 + KTOP * 16 + KTOP * 4;   // 148 KB
    if (!s_attr) {
        cudaFuncSetAttribute(nms_kernel, cudaFuncAttributeMaxDynamicSharedMemorySize, SMEM2);
        s_attr = true;
    }

    select_kernel<<<GRID1, 1024>>>(x);
    nms_kernel<<<GRID2, 1024, SMEM2>>>(x, anchors, out);
}